// round 1
// baseline (speedup 1.0000x reference)
#include <cuda_runtime.h>
#include <cstdint>

#define NF   40960
#define MDIM 256
#define NB   2048

// Transposed feature-transformer weights: ft_wT[f][m], 40960 x 256 fp32 = 41.9 MB
__device__ float g_ftwT[NF * MDIM];

// ---------------------------------------------------------------------------
// Kernel 1: tiled transpose ft_w [256, 40960] -> g_ftwT [40960, 256]
// ---------------------------------------------------------------------------
__global__ void transpose_ftw_kernel(const float* __restrict__ ft_w) {
    __shared__ float tile[32][33];
    const int f0 = blockIdx.x * 32;
    const int m0 = blockIdx.y * 32;
    const int tx = threadIdx.x;   // 0..31
    const int ty = threadIdx.y;   // 0..7

    #pragma unroll
    for (int i = 0; i < 32; i += 8) {
        // coalesced read along f
        tile[ty + i][tx] = ft_w[(size_t)(m0 + ty + i) * NF + (f0 + tx)];
    }
    __syncthreads();
    #pragma unroll
    for (int i = 0; i < 32; i += 8) {
        // coalesced write along m
        g_ftwT[(size_t)(f0 + ty + i) * MDIM + (m0 + tx)] = tile[tx][ty + i];
    }
}

// ---------------------------------------------------------------------------
// Kernel 2: one block per position. 256 threads = 8 warps.
//  Phase A: warp-ballot sparse scan of the 40960-float feature row
//  Phase B: gather-accumulate ft_wT rows (coalesced, L2-resident)
//  Phase C: tiny MLP 512->32->32->1
// ---------------------------------------------------------------------------
#define WARP_FLOATS 5120            // 40960 / 8 warps
#define WARP_VEC4   (WARP_FLOATS/4) // 1280 float4 per warp
#define SCAN_ITERS  (WARP_VEC4/32)  // 40 iterations
#define LIST_CAP    64              // per-warp nonzero capacity (lambda = 4)

__device__ __forceinline__ float clamp01(float x) {
    return fminf(fmaxf(x, 0.0f), 1.0f);
}

// Scan one color's feature row into per-warp shared index lists.
// Deterministic ordering: (warp, iteration, component, lane).
__device__ __forceinline__ void scan_features(
    const float* __restrict__ feat_row,
    int wid, int lane,
    int (*s_idx)[LIST_CAP], int* s_cnt)
{
    const float4* p = reinterpret_cast<const float4*>(feat_row) + wid * WARP_VEC4;
    int cnt = 0;
    float4 v = p[lane];
    #pragma unroll 4
    for (int it = 0; it < SCAN_ITERS; it++) {
        float4 nv;
        if (it + 1 < SCAN_ITERS) nv = p[(it + 1) * 32 + lane];  // prefetch
        const int base = wid * WARP_FLOATS + it * 128 + lane * 4;
        {
            unsigned m = __ballot_sync(0xffffffffu, v.x != 0.0f);
            int pos = cnt + __popc(m & ((1u << lane) - 1u));
            if (v.x != 0.0f && pos < LIST_CAP) s_idx[wid][pos] = base + 0;
            cnt += __popc(m);
        }
        {
            unsigned m = __ballot_sync(0xffffffffu, v.y != 0.0f);
            int pos = cnt + __popc(m & ((1u << lane) - 1u));
            if (v.y != 0.0f && pos < LIST_CAP) s_idx[wid][pos] = base + 1;
            cnt += __popc(m);
        }
        {
            unsigned m = __ballot_sync(0xffffffffu, v.z != 0.0f);
            int pos = cnt + __popc(m & ((1u << lane) - 1u));
            if (v.z != 0.0f && pos < LIST_CAP) s_idx[wid][pos] = base + 2;
            cnt += __popc(m);
        }
        {
            unsigned m = __ballot_sync(0xffffffffu, v.w != 0.0f);
            int pos = cnt + __popc(m & ((1u << lane) - 1u));
            if (v.w != 0.0f && pos < LIST_CAP) s_idx[wid][pos] = base + 3;
            cnt += __popc(m);
        }
        v = nv;
    }
    if (lane == 0) s_cnt[wid] = (cnt < LIST_CAP) ? cnt : LIST_CAP;
}

// Accumulate ft_wT rows over the compacted lists. Thread tid owns output m=tid.
__device__ __forceinline__ float accumulate_lists(
    int tid, const int (*s_idx)[LIST_CAP], const int* s_cnt, float init)
{
    float acc = init;
    #pragma unroll
    for (int w = 0; w < 8; w++) {
        const int n = s_cnt[w];
        int j = 0;
        // unroll by 2 for memory-level parallelism on the L2 gathers
        for (; j + 1 < n; j += 2) {
            const int f0 = s_idx[w][j];
            const int f1 = s_idx[w][j + 1];
            const float a = g_ftwT[f0 * MDIM + tid];
            const float b = g_ftwT[f1 * MDIM + tid];
            acc += a;
            acc += b;
        }
        if (j < n) acc += g_ftwT[s_idx[w][j] * MDIM + tid];
    }
    return acc;
}

__global__ __launch_bounds__(256) void nnue_forward_kernel(
    const float* __restrict__ wf,
    const float* __restrict__ bfeat,
    const float* __restrict__ stm,
    const float* __restrict__ ft_b,
    const float* __restrict__ l1_w,
    const float* __restrict__ l1_b,
    const float* __restrict__ l2_w,
    const float* __restrict__ l2_b,
    const float* __restrict__ l3_w,
    const float* __restrict__ l3_b,
    float* __restrict__ out)
{
    const int b    = blockIdx.x;
    const int tid  = threadIdx.x;
    const int wid  = tid >> 5;
    const int lane = tid & 31;

    __shared__ int   s_idx[8][LIST_CAP];
    __shared__ int   s_cnt[8];
    __shared__ float s_h[512];
    __shared__ float s_l2x[32];   // clip(l1_x @ l1_w.T + l1_b)

    const float bias = ft_b[tid];

    // ---- white accumulator ----
    scan_features(wf + (size_t)b * NF, wid, lane, s_idx, s_cnt);
    __syncthreads();
    float accW = accumulate_lists(tid, s_idx, s_cnt, bias);
    __syncthreads();  // done reading s_idx before black scan overwrites

    // ---- black accumulator ----
    scan_features(bfeat + (size_t)b * NF, wid, lane, s_idx, s_cnt);
    __syncthreads();
    float accB = accumulate_lists(tid, s_idx, s_cnt, bias);

    // ---- stm blend + clip -> hidden vector of 512 ----
    const float s = stm[b];
    const float h1 = clamp01(s * accW + (1.0f - s) * accB);
    const float h2 = clamp01(s * accB + (1.0f - s) * accW);
    s_h[tid]       = h1;
    s_h[256 + tid] = h2;
    __syncthreads();

    // ---- L1: 512 -> 32.  n = tid>>3 owns output n; 8 threads per output. ----
    {
        const int n   = tid >> 3;
        const int seg = tid & 7;
        const float4* wrow = reinterpret_cast<const float4*>(l1_w + n * 512 + seg * 64);
        const float4* hv   = reinterpret_cast<const float4*>(s_h) + seg * 16;
        float p = 0.0f;
        #pragma unroll
        for (int i = 0; i < 16; i++) {
            const float4 a = wrow[i];
            const float4 x = hv[i];
            p += a.x * x.x;
            p += a.y * x.y;
            p += a.z * x.z;
            p += a.w * x.w;
        }
        // reduce the 8 partials (aligned 8-lane groups within a warp)
        p += __shfl_down_sync(0xffffffffu, p, 4);
        p += __shfl_down_sync(0xffffffffu, p, 2);
        p += __shfl_down_sync(0xffffffffu, p, 1);
        if (seg == 0) s_l2x[n] = clamp01(p + l1_b[n]);
    }
    __syncthreads();

    // ---- L2 (32->32), L3 (32->1), eval scaling.  Warp 0 only. ----
    if (tid < 32) {
        float q = l2_b[tid];
        #pragma unroll
        for (int k = 0; k < 32; k++) q += l2_w[tid * 32 + k] * s_l2x[k];
        const float l3x = clamp01(q);
        float t = l3x * l3_w[tid];
        #pragma unroll
        for (int off = 16; off > 0; off >>= 1)
            t += __shfl_down_sync(0xffffffffu, t, off);
        if (tid == 0) {
            const float ev = clamp01(t + l3_b[0]);
            out[b] = (ev - 0.5f) * 2.0f * 10000.0f;
        }
    }
}

// ---------------------------------------------------------------------------
// Launch
// ---------------------------------------------------------------------------
extern "C" void kernel_launch(void* const* d_in, const int* in_sizes, int n_in,
                              void* d_out, int out_size)
{
    const float* wf    = (const float*)d_in[0];
    const float* bfeat = (const float*)d_in[1];
    const float* stm   = (const float*)d_in[2];
    const float* ft_w  = (const float*)d_in[3];
    const float* ft_b  = (const float*)d_in[4];
    const float* l1_w  = (const float*)d_in[5];
    const float* l1_b  = (const float*)d_in[6];
    const float* l2_w  = (const float*)d_in[7];
    const float* l2_b  = (const float*)d_in[8];
    const float* l3_w  = (const float*)d_in[9];
    const float* l3_b  = (const float*)d_in[10];
    float* out = (float*)d_out;

    // 1) Transpose ft_w -> g_ftwT (L2-resident gather table)
    dim3 tgrid(NF / 32, MDIM / 32);
    dim3 tblock(32, 8);
    transpose_ftw_kernel<<<tgrid, tblock>>>(ft_w);

    // 2) Sparse NNUE forward, one CTA per position
    nnue_forward_kernel<<<NB, 256>>>(wf, bfeat, stm, ft_b, l1_w, l1_b,
                                     l2_w, l2_b, l3_w, l3_b, out);
}

// round 2
// speedup vs baseline: 1.2400x; 1.2400x over previous
#include <cuda_runtime.h>
#include <cstdint>

#define NF    40960
#define MDIM  256
#define NB    2048
#define ROWS  (2*NB)          // 4096 feature rows (white then black)
#define PARTS 2               // warps per row
#define HALF_VEC4 5120        // float4s per half row (10240/2)
#define BATCH 8               // float4s loaded per inner batch
#define NBATCH (HALF_VEC4/32/BATCH)  // 20 batches per half-row warp

// Transposed feature-transformer weights: ft_wT[f][m], 40960 x 256 fp32 = 41.9 MB
__device__ float g_ftwT[NF * MDIM];
// Partial accumulators: [part][row][m]  (2 x 4096 x 256 fp32 = 8 MB)
__device__ float g_acc[PARTS * ROWS * MDIM];

// ---------------------------------------------------------------------------
// Kernel 1: tiled transpose ft_w [256, 40960] -> g_ftwT [40960, 256]
// ---------------------------------------------------------------------------
__global__ void transpose_ftw_kernel(const float* __restrict__ ft_w) {
    __shared__ float tile[32][33];
    const int f0 = blockIdx.x * 32;
    const int m0 = blockIdx.y * 32;
    const int tx = threadIdx.x;   // 0..31
    const int ty = threadIdx.y;   // 0..7

    #pragma unroll
    for (int i = 0; i < 32; i += 8)
        tile[ty + i][tx] = ft_w[(size_t)(m0 + ty + i) * NF + (f0 + tx)];
    __syncthreads();
    #pragma unroll
    for (int i = 0; i < 32; i += 8)
        g_ftwT[(size_t)(f0 + ty + i) * MDIM + (m0 + tx)] = tile[tx][ty + i];
}

// ---------------------------------------------------------------------------
// Kernel 2: fused sparse scan + gather-accumulate.
// One warp per (row, half). Accumulators live in registers:
//   lane l holds m = 4l..4l+3 (acc0) and m = 128+4l..128+4l+3 (acc1).
// Deterministic order: fixed batch order, fixed ballot bit order.
// ---------------------------------------------------------------------------
__global__ __launch_bounds__(256) void scan_accum_kernel(
    const float* __restrict__ wf,
    const float* __restrict__ bfeat)
{
    const int gw   = (blockIdx.x * blockDim.x + threadIdx.x) >> 5;  // 0..8191
    const int lane = threadIdx.x & 31;
    const int row  = gw >> 1;           // 0..4095
    const int part = gw & 1;            // half of the row

    const float* rowp = (row < NB) ? (wf + (size_t)row * NF)
                                   : (bfeat + (size_t)(row - NB) * NF);
    const float4* p = reinterpret_cast<const float4*>(rowp) + part * HALF_VEC4;
    const int fbase_part = part * (HALF_VEC4 * 4);   // float-index offset of this half

    float4 acc0 = make_float4(0.f, 0.f, 0.f, 0.f);
    float4 acc1 = make_float4(0.f, 0.f, 0.f, 0.f);

    #pragma unroll 1
    for (int bt = 0; bt < NBATCH; bt++) {
        // batched streaming loads (evict-first: keep ft_wT resident in L2)
        float4 v[BATCH];
        #pragma unroll
        for (int u = 0; u < BATCH; u++)
            v[u] = __ldcs(&p[(bt * BATCH + u) * 32 + lane]);

        #pragma unroll
        for (int u = 0; u < BATCH; u++) {
            // features are exactly 0.0 or 1.0 -> sum>0 iff any nonzero
            const float sum = v[u].x + v[u].y + v[u].z + v[u].w;
            unsigned bal = __ballot_sync(0xffffffffu, sum != 0.0f);
            if (bal) {
                const int base0 = fbase_part + (bt * BATCH + u) * 128;  // float idx of lane 0
                do {
                    const int s = __ffs(bal) - 1;
                    bal &= bal - 1;
                    // fetch the source lane's 4 values
                    const float sx = __shfl_sync(0xffffffffu, v[u].x, s);
                    const float sy = __shfl_sync(0xffffffffu, v[u].y, s);
                    const float sz = __shfl_sync(0xffffffffu, v[u].z, s);
                    const float sw = __shfl_sync(0xffffffffu, v[u].w, s);
                    const int fb = base0 + s * 4;
                    #pragma unroll
                    for (int c = 0; c < 4; c++) {
                        const float val = (c == 0) ? sx : (c == 1) ? sy : (c == 2) ? sz : sw;
                        if (val != 0.0f) {
                            const float4* wrow =
                                reinterpret_cast<const float4*>(g_ftwT + (size_t)(fb + c) * MDIM);
                            const float4 w0 = wrow[lane];
                            const float4 w1 = wrow[32 + lane];
                            acc0.x += w0.x; acc0.y += w0.y; acc0.z += w0.z; acc0.w += w0.w;
                            acc1.x += w1.x; acc1.y += w1.y; acc1.z += w1.z; acc1.w += w1.w;
                        }
                    }
                } while (bal);
            }
        }
    }

    float4* outp = reinterpret_cast<float4*>(g_acc + ((size_t)part * ROWS + row) * MDIM);
    outp[lane]      = acc0;
    outp[32 + lane] = acc1;
}

// ---------------------------------------------------------------------------
// Kernel 3: combine partials + bias, stm blend + clip, MLP 512->32->32->1
// ---------------------------------------------------------------------------
__device__ __forceinline__ float clamp01(float x) {
    return fminf(fmaxf(x, 0.0f), 1.0f);
}

__global__ __launch_bounds__(256) void mlp_tail_kernel(
    const float* __restrict__ stm,
    const float* __restrict__ ft_b,
    const float* __restrict__ l1_w,
    const float* __restrict__ l1_b,
    const float* __restrict__ l2_w,
    const float* __restrict__ l2_b,
    const float* __restrict__ l3_w,
    const float* __restrict__ l3_b,
    float* __restrict__ out)
{
    const int b   = blockIdx.x;
    const int tid = threadIdx.x;

    __shared__ float s_h[512];
    __shared__ float s_l2x[32];

    const float bias = ft_b[tid];
    const float accW = g_acc[(size_t)b * MDIM + tid]
                     + g_acc[((size_t)ROWS + b) * MDIM + tid] + bias;
    const float accB = g_acc[((size_t)NB + b) * MDIM + tid]
                     + g_acc[((size_t)ROWS + NB + b) * MDIM + tid] + bias;

    const float s  = stm[b];
    s_h[tid]       = clamp01(s * accW + (1.0f - s) * accB);
    s_h[256 + tid] = clamp01(s * accB + (1.0f - s) * accW);
    __syncthreads();

    // L1: 512 -> 32. Output n = tid>>3; 8 threads per output.
    {
        const int n   = tid >> 3;
        const int seg = tid & 7;
        const float4* wrow = reinterpret_cast<const float4*>(l1_w + n * 512 + seg * 64);
        const float4* hv   = reinterpret_cast<const float4*>(s_h) + seg * 16;
        float psum = 0.0f;
        #pragma unroll
        for (int i = 0; i < 16; i++) {
            const float4 a = wrow[i];
            const float4 x = hv[i];
            psum += a.x * x.x;
            psum += a.y * x.y;
            psum += a.z * x.z;
            psum += a.w * x.w;
        }
        psum += __shfl_down_sync(0xffffffffu, psum, 4);
        psum += __shfl_down_sync(0xffffffffu, psum, 2);
        psum += __shfl_down_sync(0xffffffffu, psum, 1);
        if (seg == 0) s_l2x[n] = clamp01(psum + l1_b[n]);
    }
    __syncthreads();

    // L2 (32->32), L3 (32->1), eval scaling. Warp 0 only.
    if (tid < 32) {
        float q = l2_b[tid];
        #pragma unroll
        for (int k = 0; k < 32; k++) q += l2_w[tid * 32 + k] * s_l2x[k];
        const float l3x = clamp01(q);
        float t = l3x * l3_w[tid];
        #pragma unroll
        for (int off = 16; off > 0; off >>= 1)
            t += __shfl_down_sync(0xffffffffu, t, off);
        if (tid == 0) {
            const float ev = clamp01(t + l3_b[0]);
            out[b] = (ev - 0.5f) * 2.0f * 10000.0f;
        }
    }
}

// ---------------------------------------------------------------------------
// Launch
// ---------------------------------------------------------------------------
extern "C" void kernel_launch(void* const* d_in, const int* in_sizes, int n_in,
                              void* d_out, int out_size)
{
    const float* wf    = (const float*)d_in[0];
    const float* bfeat = (const float*)d_in[1];
    const float* stm   = (const float*)d_in[2];
    const float* ft_w  = (const float*)d_in[3];
    const float* ft_b  = (const float*)d_in[4];
    const float* l1_w  = (const float*)d_in[5];
    const float* l1_b  = (const float*)d_in[6];
    const float* l2_w  = (const float*)d_in[7];
    const float* l2_b  = (const float*)d_in[8];
    const float* l3_w  = (const float*)d_in[9];
    const float* l3_b  = (const float*)d_in[10];
    float* out = (float*)d_out;

    // 1) Transpose ft_w -> g_ftwT (L2-resident gather table)
    dim3 tgrid(NF / 32, MDIM / 32);
    dim3 tblock(32, 8);
    transpose_ftw_kernel<<<tgrid, tblock>>>(ft_w);

    // 2) Fused sparse scan + gather: 8192 warps (one per half-row)
    const int total_warps = ROWS * PARTS;              // 8192
    scan_accum_kernel<<<total_warps / 8, 256>>>(wf, bfeat);

    // 3) Blend + MLP tail
    mlp_tail_kernel<<<NB, 256>>>(stm, ft_b, l1_w, l1_b, l2_w, l2_b,
                                 l3_w, l3_b, out);
}